// round 14
// baseline (speedup 1.0000x reference)
#include <cuda_runtime.h>
#include <cuda_fp16.h>
#include <math.h>

#define NN 100000
#define NE_MAX 1600000
#define CAP 64                 /* per-node bucket capacity; deg ~ Poisson(16) */

#define INV_SQRT_MUL 0.17677669529663687f   /* 1/sqrt(32)  */
#define C_DOT        0.10206207261596575f   /* 1/sqrt(96)  */
#define C_SCL        0.07216878364870323f   /* 1/sqrt(192) */
#define C_CRS        0.05103103630798287f   /* 1/sqrt(384) */
#define SQRT3        1.7320508075688772f

// Scratch (__device__ globals; everything rewritten each launch)
// g_feat[n*32+i] = uint2{ half2(s,vx), half2(vy,vz) }  -- 8B per channel
static __device__ __align__(16) uint2 g_feat[(size_t)NN * 32];
static __device__ __align__(16) float4 g_bucket[(size_t)NN * CAP];// per-node edge recs
static __device__ __align__(16) float4 g_pos4[NN];                // padded positions
static __device__ int g_cur[NN];
static __device__ float g_WA[1024];
static __device__ __align__(8) float2 g_WBC[1024];                // (WB, WC)

// ---------------------------------------------------------------------------
// K1: node transform, 4 nodes per warp (weights amortized), 32 nodes/block.
// Rows repacked in smem to float4 (s,vx,vy,vz) per channel -> ONE broadcast
// LDS.128 per (node,i) in the hot loop. fp16 packed output.
// Also zeroes g_cur and pads pos into g_pos4 (1 node/thread).
// ---------------------------------------------------------------------------
__global__ void __launch_bounds__(256, 6) k_node(const float* __restrict__ x,
                                                 const float* __restrict__ pos,
                                                 const float* __restrict__ Wns,
                                                 const float* __restrict__ Wnv) {
    int gid = blockIdx.x * 256 + threadIdx.x;
    if (gid < NN) {
        g_cur[gid] = 0;
        g_pos4[gid] = make_float4(pos[3 * gid], pos[3 * gid + 1], pos[3 * gid + 2], 0.f);
    }

    __shared__ float ws0[1024], ws1[1024], wvv[1024];
    __shared__ float4 sf[32][32];   // [slot][i] = (s, vx, vy, vz)
    for (int t = threadIdx.x; t < 1024; t += 256) {
        int i = t >> 5, j = t & 31;
        ws0[t] = Wns[i * 64 + j] * INV_SQRT_MUL;
        ws1[t] = Wns[i * 64 + 32 + j] * INV_SQRT_MUL;
        wvv[t] = Wnv[t] * INV_SQRT_MUL;
    }
    __syncthreads();

    int w = threadIdx.x >> 5, lane = threadIdx.x & 31;
    int n0 = blockIdx.x * 32 + w * 4;       // 3125 blocks * 32 = NN exactly

    // ---- stage: raw rows -> repack to (s,vx,vy,vz) per channel ----
#pragma unroll
    for (int g = 0; g < 4; g++)
        sf[w * 4 + g][lane] =
            reinterpret_cast<const float4*>(x)[(size_t)(n0 + g) * 32 + lane];
    __syncwarp();
    float4 pk[4];
#pragma unroll
    for (int g = 0; g < 4; g++) {
        const float* flat = (const float*)&sf[w * 4 + g][0];
        pk[g] = make_float4(flat[lane], flat[32 + 3 * lane],
                            flat[33 + 3 * lane], flat[34 + 3 * lane]);
    }
    __syncwarp();
#pragma unroll
    for (int g = 0; g < 4; g++) sf[w * 4 + g][lane] = pk[g];
    __syncwarp();

    // ---- hot loop: 3 weight LDS + 4 broadcast LDS.128 per i ----
    float h0[4], h1[4], hx[4], hy[4], hz[4];
#pragma unroll
    for (int g = 0; g < 4; g++) { h0[g] = 0.f; h1[g] = 0.f; hx[g] = 0.f; hy[g] = 0.f; hz[g] = 0.f; }

#pragma unroll 4
    for (int i = 0; i < 32; i++) {
        float w0 = ws0[i * 32 + lane];
        float w1 = ws1[i * 32 + lane];
        float wv = wvv[i * 32 + lane];
#pragma unroll
        for (int g = 0; g < 4; g++) {
            float4 f = sf[w * 4 + g][i];        // broadcast LDS.128
            h0[g] += f.x * w0;
            h1[g] += f.x * w1;
            hx[g] += f.y * wv; hy[g] += f.z * wv; hz[g] += f.w * wv;
        }
    }
#pragma unroll
    for (int g = 0; g < 4; g++) {
        float sc = fmaxf(h0[g], 0.f);
        float gt = 1.f / (1.f + __expf(-h1[g]));
        __half2 pa = __floats2half2_rn(sc, hx[g] * gt);
        __half2 pb = __floats2half2_rn(hy[g] * gt, hz[g] * gt);
        uint2 u;
        u.x = *reinterpret_cast<unsigned int*>(&pa);
        u.y = *reinterpret_cast<unsigned int*>(&pb);
        g_feat[(size_t)(n0 + g) * 32 + lane] = u;
    }
}

// ---------------------------------------------------------------------------
// K2: scatter edges into per-row buckets (atomic slot grab), 1 edge/thread,
// padded-pos gathers. Weight fold rides on the last block (low regs, no smem).
// ---------------------------------------------------------------------------
__global__ void k_scatter(const int* __restrict__ ei, int E,
                          const float* __restrict__ Wd, const float* __restrict__ Ws,
                          const float* __restrict__ Wc, const float* __restrict__ Wms,
                          const float* __restrict__ Wmv) {
    if (blockIdx.x == gridDim.x - 1) {
        // ---- weight fold: WA = Wd@Wms, WB = Ws@Wmv, WC = Wc@Wmv (scaled) ----
#pragma unroll 1
        for (int t = threadIdx.x; t < 1024; t += 256) {
            int i = t >> 5, j = t & 31;
            float a = 0.f, b = 0.f, c = 0.f;
#pragma unroll
            for (int k = 0; k < 32; k++) {
                float ms = Wms[k * 32 + j], mv = Wmv[k * 32 + j];
                a += Wd[i * 32 + k] * ms;
                b += Ws[i * 32 + k] * mv;
                c += Wc[i * 32 + k] * mv;
            }
            g_WA[t]  = a * (C_DOT * INV_SQRT_MUL);
            g_WBC[t] = make_float2(b * (C_SCL * INV_SQRT_MUL),
                                   c * (C_CRS * INV_SQRT_MUL));
        }
        return;
    }
    int e = blockIdx.x * 256 + threadIdx.x;
    if (e >= E) return;
    int r = __ldg(ei + e);
    int c = __ldg(ei + E + e);
    float4 pc = __ldg(&g_pos4[c]);
    float4 pr = __ldg(&g_pos4[r]);
    float rx = pc.x - pr.x;
    float ry = pc.y - pr.y;
    float rz = pc.z - pr.z;
    float inv = rsqrtf(rx * rx + ry * ry + rz * rz + 1e-12f) * SQRT3;
    // u = sqrt(3) * unit[(1,2,0)]
    float4 rec = make_float4(ry * inv, rz * inv, rx * inv, __int_as_float(c));
    int p = atomicAdd(&g_cur[r], 1);
    if (p < CAP) g_bucket[(size_t)r * CAP + p] = rec;
}

// ---------------------------------------------------------------------------
// K3: fused aggregate + message transform + LayerNorm + residual.
// Warp handles TWO nodes. Both counts + both first bucket chunks prefetched
// unconditionally up front (one exposed round-trip instead of four); common
// case (deg<=32) runs entirely from smem with no per-chunk syncs. fp16
// feature gathers; contraction streams WA + (WB,WC); LN staged in dead smem.
// ---------------------------------------------------------------------------
__device__ __forceinline__ void ln_write(int n, float aS, float aX, float aY, float aZ,
                                         const float* __restrict__ x,
                                         const float* sg, const float* sb,
                                         float* __restrict__ out, int lane,
                                         float* buf /* 256 floats */) {
    float4* bufA4 = (float4*)buf;            // x row
    float*  bufB  = buf + 128;               // out row
    bufA4[lane] = reinterpret_cast<const float4*>(x)[(size_t)n * 32 + lane];
    float sum = aS + aX + aY + aZ;
    float sq  = aS * aS + aX * aX + aY * aY + aZ * aZ;
#pragma unroll
    for (int o = 16; o > 0; o >>= 1) {
        sum += __shfl_xor_sync(0xffffffffu, sum, o);
        sq  += __shfl_xor_sync(0xffffffffu, sq, o);
    }
    float mean = sum * (1.f / 128.f);
    float var  = sq * (1.f / 128.f) - mean * mean;
    float rstd = rsqrtf(fmaxf(var, 0.f) + 1e-5f);
    __syncwarp();
    bufB[lane] = buf[lane] + (aS - mean) * rstd * sg[lane] + sb[lane];
    int p = 32 + 3 * lane;
    bufB[p]     = buf[p]     + (aX - mean) * rstd * sg[p]     + sb[p];
    bufB[p + 1] = buf[p + 1] + (aY - mean) * rstd * sg[p + 1] + sb[p + 1];
    bufB[p + 2] = buf[p + 2] + (aZ - mean) * rstd * sg[p + 2] + sb[p + 2];
    __syncwarp();
    reinterpret_cast<float4*>(out)[(size_t)n * 32 + lane] = ((float4*)bufB)[lane];
}

__global__ void __launch_bounds__(256, 6) k_aggregate(const float* __restrict__ x,
                                                      const float* __restrict__ gamma,
                                                      const float* __restrict__ beta,
                                                      float* __restrict__ out) {
    __shared__ float4 srec[2][8][32];     // prefetched first chunks, both nodes
    __shared__ float4 smom[16][32][2];    // [nodeSlot][i][2]; reused as LN buffers
    __shared__ float sg[128], sb[128];
    for (int t = threadIdx.x; t < 128; t += 256) { sg[t] = gamma[t]; sb[t] = beta[t]; }
    int w = threadIdx.x >> 5;
    int lane = threadIdx.x & 31;

    // ---- prefetch: counts + first 32 recs of BOTH nodes, all in flight ----
    int n0 = blockIdx.x * 16 + w;
    int n1 = n0 + 8;
    int c0 = g_cur[n0];
    int c1 = g_cur[n1];
    srec[0][w][lane] = __ldg(&g_bucket[(size_t)n0 * CAP + lane]);  // garbage slots
    srec[1][w][lane] = __ldg(&g_bucket[(size_t)n1 * CAP + lane]);  // never read
    __syncthreads();   // covers sg/sb too

    // ---- edge-moment phase for two nodes ----
#pragma unroll 1
    for (int half = 0; half < 2; half++) {
        int n = half ? n1 : n0;
        int count = min(half ? c1 : c0, CAP);
        float aD = 0.f, aBx = 0.f, aBy = 0.f, aBz = 0.f, aCx = 0.f, aCy = 0.f, aCz = 0.f;
        // chunk 0 (already staged; covers all but ~1e-5 of nodes)
        int m = min(32, count);
#pragma unroll 4
        for (int k = 0; k < m; k++) {
            float4 r = srec[half][w][k];
            int c = __float_as_int(r.w);
            uint2 u = __ldg(&g_feat[(size_t)c * 32 + lane]);   // fp16x4
            float2 fa = __half22float2(*reinterpret_cast<__half2*>(&u.x)); // (s,vx)
            float2 fb = __half22float2(*reinterpret_cast<__half2*>(&u.y)); // (vy,vz)
            float fs = fa.x, vx = fa.y, vy = fb.x, vz = fb.y;
            aD  += vx * r.x + vy * r.y + vz * r.z;
            aBx += fs * r.x; aBy += fs * r.y; aBz += fs * r.z;
            aCx += vy * r.z - vz * r.y;
            aCy += vz * r.x - vx * r.z;
            aCz += vx * r.y - vy * r.x;
        }
        // rare tail chunks (deg > 32)
        for (int base = 32; base < count; base += 32) {
            __syncwarp();
            if (base + lane < count)
                srec[half][w][lane] = __ldg(&g_bucket[(size_t)n * CAP + base + lane]);
            __syncwarp();
            int mm = min(32, count - base);
            for (int k = 0; k < mm; k++) {
                float4 r = srec[half][w][k];
                int c = __float_as_int(r.w);
                uint2 u = __ldg(&g_feat[(size_t)c * 32 + lane]);
                float2 fa = __half22float2(*reinterpret_cast<__half2*>(&u.x));
                float2 fb = __half22float2(*reinterpret_cast<__half2*>(&u.y));
                float fs = fa.x, vx = fa.y, vy = fb.x, vz = fb.y;
                aD  += vx * r.x + vy * r.y + vz * r.z;
                aBx += fs * r.x; aBy += fs * r.y; aBz += fs * r.z;
                aCx += vy * r.z - vz * r.y;
                aCy += vz * r.x - vx * r.z;
                aCz += vx * r.y - vy * r.x;
            }
        }
        float invd = 1.f / fmaxf((float)count, 1.f);
        smom[half * 8 + w][lane][0] = make_float4(aD * invd, aBx * invd, aBy * invd, aBz * invd);
        smom[half * 8 + w][lane][1] = make_float4(aCx * invd, aCy * invd, aCz * invd, 0.f);
    }
    __syncwarp();

    // ---- contraction for both nodes; WA scalar + (WB,WC) paired loads ----
    float aS0 = 0.f, aX0 = 0.f, aY0 = 0.f, aZ0 = 0.f;
    float aS1 = 0.f, aX1 = 0.f, aY1 = 0.f, aZ1 = 0.f;
#pragma unroll
    for (int i = 0; i < 32; i++) {
        float  WAi = __ldg(&g_WA[i * 32 + lane]);
        float2 Wbc = __ldg(&g_WBC[i * 32 + lane]);
        float4 p0 = smom[w][i][0];       // broadcast LDS
        float4 p1 = smom[w][i][1];
        float4 q0 = smom[8 + w][i][0];
        float4 q1 = smom[8 + w][i][1];
        aS0 += p0.x * WAi;
        aX0 += p0.y * Wbc.x + p1.x * Wbc.y;
        aY0 += p0.z * Wbc.x + p1.y * Wbc.y;
        aZ0 += p0.w * Wbc.x + p1.z * Wbc.y;
        aS1 += q0.x * WAi;
        aX1 += q0.y * Wbc.x + q1.x * Wbc.y;
        aY1 += q0.z * Wbc.x + q1.y * Wbc.y;
        aZ1 += q0.w * Wbc.x + q1.z * Wbc.y;
    }
    __syncwarp();   // smom now dead; reuse as LN staging

    ln_write(n0, aS0, aX0, aY0, aZ0, x, sg, sb, out, lane, (float*)&smom[w][0][0]);
    ln_write(n1, aS1, aX1, aY1, aZ1, x, sg, sb, out, lane, (float*)&smom[8 + w][0][0]);
}

// ---------------------------------------------------------------------------
extern "C" void kernel_launch(void* const* d_in, const int* in_sizes, int n_in,
                              void* d_out, int out_size) {
    const float* x    = (const float*)d_in[0];
    const float* pos  = (const float*)d_in[1];
    const int*   ei   = (const int*)d_in[2];
    const float* Wns  = (const float*)d_in[3];
    const float* Wnv  = (const float*)d_in[4];
    const float* Wd   = (const float*)d_in[5];
    const float* Ws   = (const float*)d_in[6];
    const float* Wc   = (const float*)d_in[7];
    const float* Wms  = (const float*)d_in[8];
    const float* Wmv  = (const float*)d_in[9];
    const float* gam  = (const float*)d_in[10];
    const float* bet  = (const float*)d_in[11];
    float* out = (float*)d_out;

    int E = in_sizes[2] / 2;

    k_node<<<NN / 32, 256>>>(x, pos, Wns, Wnv);
    k_scatter<<<(E + 255) / 256 + 1, 256>>>(ei, E, Wd, Ws, Wc, Wms, Wmv);
    k_aggregate<<<NN / 16, 256>>>(x, gam, bet, out);
}

// round 15
// speedup vs baseline: 1.0565x; 1.0565x over previous
#include <cuda_runtime.h>
#include <cuda_fp16.h>
#include <math.h>

#define NN 100000
#define NE_MAX 1600000
#define CAP 64                 /* per-node bucket capacity; deg ~ Poisson(16) */

#define INV_SQRT_MUL 0.17677669529663687f   /* 1/sqrt(32)  */
#define C_DOT        0.10206207261596575f   /* 1/sqrt(96)  */
#define C_SCL        0.07216878364870323f   /* 1/sqrt(192) */
#define C_CRS        0.05103103630798287f   /* 1/sqrt(384) */
#define SQRT3        1.7320508075688772f

// Scratch (__device__ globals; everything rewritten each launch)
// g_feat[n*32+i] = uint2{ half2(s,vx), half2(vy,vz) }  -- 8B per channel
static __device__ __align__(16) uint2 g_feat[(size_t)NN * 32];
static __device__ __align__(16) float4 g_bucket[(size_t)NN * CAP];// per-node edge recs
static __device__ __align__(16) float4 g_pos4[NN];                // padded positions
static __device__ int g_cur[NN];
static __device__ float g_WA[1024];
static __device__ __align__(8) float2 g_WBC[1024];                // (WB, WC)

// ---------------------------------------------------------------------------
// K0: pos padding (blocks 0..390, coalesced) + weight fold (last block).
// WA = Wd@Wms, WB = Ws@Wmv, WC = Wc@Wmv (scale constants baked in).
// ---------------------------------------------------------------------------
__global__ void __launch_bounds__(256) k_prep(const float* __restrict__ pos,
                                              const float* __restrict__ Wd,
                                              const float* __restrict__ Ws,
                                              const float* __restrict__ Wc,
                                              const float* __restrict__ Wms,
                                              const float* __restrict__ Wmv) {
    if (blockIdx.x < (NN + 255) / 256) {
        int n = blockIdx.x * 256 + threadIdx.x;
        if (n < NN)
            g_pos4[n] = make_float4(pos[3 * n], pos[3 * n + 1], pos[3 * n + 2], 0.f);
        return;
    }
    // ---- weight fold (256 threads handle 1024 entries) ----
#pragma unroll 1
    for (int t = threadIdx.x; t < 1024; t += 256) {
        int i = t >> 5, j = t & 31;
        float a = 0.f, b = 0.f, c = 0.f;
#pragma unroll
        for (int k = 0; k < 32; k++) {
            float ms = Wms[k * 32 + j], mv = Wmv[k * 32 + j];
            a += Wd[i * 32 + k] * ms;
            b += Ws[i * 32 + k] * mv;
            c += Wc[i * 32 + k] * mv;
        }
        g_WA[t]  = a * (C_DOT * INV_SQRT_MUL);
        g_WBC[t] = make_float2(b * (C_SCL * INV_SQRT_MUL),
                               c * (C_CRS * INV_SQRT_MUL));
    }
}

// ---------------------------------------------------------------------------
// K1: node transform, 4 nodes per warp (weights amortized), 32 nodes/block.
// Rows repacked in smem to float4 (s,vx,vy,vz) per channel -> ONE broadcast
// LDS.128 per (node,i) in the hot loop. fp16 packed output.
// Also zeroes g_cur (1 elem/thread).
// ---------------------------------------------------------------------------
__global__ void __launch_bounds__(256, 6) k_node(const float* __restrict__ x,
                                                 const float* __restrict__ Wns,
                                                 const float* __restrict__ Wnv) {
    int gid = blockIdx.x * 256 + threadIdx.x;
    if (gid < NN) g_cur[gid] = 0;

    __shared__ float ws0[1024], ws1[1024], wvv[1024];
    __shared__ float4 sf[32][32];   // [slot][i] = (s, vx, vy, vz)
    for (int t = threadIdx.x; t < 1024; t += 256) {
        int i = t >> 5, j = t & 31;
        ws0[t] = Wns[i * 64 + j] * INV_SQRT_MUL;
        ws1[t] = Wns[i * 64 + 32 + j] * INV_SQRT_MUL;
        wvv[t] = Wnv[t] * INV_SQRT_MUL;
    }
    __syncthreads();

    int w = threadIdx.x >> 5, lane = threadIdx.x & 31;
    int n0 = blockIdx.x * 32 + w * 4;       // 3125 blocks * 32 = NN exactly

    // ---- stage: raw rows -> repack to (s,vx,vy,vz) per channel ----
#pragma unroll
    for (int g = 0; g < 4; g++)
        sf[w * 4 + g][lane] =
            reinterpret_cast<const float4*>(x)[(size_t)(n0 + g) * 32 + lane];
    __syncwarp();
    float4 pk[4];
#pragma unroll
    for (int g = 0; g < 4; g++) {
        const float* flat = (const float*)&sf[w * 4 + g][0];
        pk[g] = make_float4(flat[lane], flat[32 + 3 * lane],
                            flat[33 + 3 * lane], flat[34 + 3 * lane]);
    }
    __syncwarp();
#pragma unroll
    for (int g = 0; g < 4; g++) sf[w * 4 + g][lane] = pk[g];
    __syncwarp();

    // ---- hot loop: 3 weight LDS + 4 broadcast LDS.128 per i ----
    float h0[4], h1[4], hx[4], hy[4], hz[4];
#pragma unroll
    for (int g = 0; g < 4; g++) { h0[g] = 0.f; h1[g] = 0.f; hx[g] = 0.f; hy[g] = 0.f; hz[g] = 0.f; }

#pragma unroll 4
    for (int i = 0; i < 32; i++) {
        float w0 = ws0[i * 32 + lane];
        float w1 = ws1[i * 32 + lane];
        float wv = wvv[i * 32 + lane];
#pragma unroll
        for (int g = 0; g < 4; g++) {
            float4 f = sf[w * 4 + g][i];        // broadcast LDS.128
            h0[g] += f.x * w0;
            h1[g] += f.x * w1;
            hx[g] += f.y * wv; hy[g] += f.z * wv; hz[g] += f.w * wv;
        }
    }
#pragma unroll
    for (int g = 0; g < 4; g++) {
        float sc = fmaxf(h0[g], 0.f);
        float gt = 1.f / (1.f + __expf(-h1[g]));
        __half2 pa = __floats2half2_rn(sc, hx[g] * gt);
        __half2 pb = __floats2half2_rn(hy[g] * gt, hz[g] * gt);
        uint2 u;
        u.x = *reinterpret_cast<unsigned int*>(&pa);
        u.y = *reinterpret_cast<unsigned int*>(&pb);
        g_feat[(size_t)(n0 + g) * 32 + lane] = u;
    }
}

// ---------------------------------------------------------------------------
// K2: scatter edges into per-row buckets (atomic slot grab), 1 edge/thread.
// pos gathers via padded float4 (1 wavefront per endpoint instead of 3).
// ---------------------------------------------------------------------------
__global__ void k_scatter(const int* __restrict__ ei, int E) {
    int e = blockIdx.x * 256 + threadIdx.x;
    if (e >= E) return;
    int r = __ldg(ei + e);
    int c = __ldg(ei + E + e);
    float4 pc = __ldg(&g_pos4[c]);
    float4 pr = __ldg(&g_pos4[r]);
    float rx = pc.x - pr.x;
    float ry = pc.y - pr.y;
    float rz = pc.z - pr.z;
    float inv = rsqrtf(rx * rx + ry * ry + rz * rz + 1e-12f) * SQRT3;
    // u = sqrt(3) * unit[(1,2,0)]
    float4 rec = make_float4(ry * inv, rz * inv, rx * inv, __int_as_float(c));
    int p = atomicAdd(&g_cur[r], 1);
    if (p < CAP) g_bucket[(size_t)r * CAP + p] = rec;
}

// ---------------------------------------------------------------------------
// K3: fused aggregate + message transform + LayerNorm + residual.
// Warp handles TWO nodes. Counts + first bucket chunks of both nodes
// prefetched up front (one exposed round-trip instead of four); common case
// (deg<=32) runs from smem with no per-chunk syncs. 7 blocks/SM occupancy.
// ---------------------------------------------------------------------------
__device__ __forceinline__ void ln_write(int n, float aS, float aX, float aY, float aZ,
                                         const float* __restrict__ x,
                                         const float* sg, const float* sb,
                                         float* __restrict__ out, int lane,
                                         float* buf /* 256 floats */) {
    float4* bufA4 = (float4*)buf;            // x row
    float*  bufB  = buf + 128;               // out row
    bufA4[lane] = reinterpret_cast<const float4*>(x)[(size_t)n * 32 + lane];
    float sum = aS + aX + aY + aZ;
    float sq  = aS * aS + aX * aX + aY * aY + aZ * aZ;
#pragma unroll
    for (int o = 16; o > 0; o >>= 1) {
        sum += __shfl_xor_sync(0xffffffffu, sum, o);
        sq  += __shfl_xor_sync(0xffffffffu, sq, o);
    }
    float mean = sum * (1.f / 128.f);
    float var  = sq * (1.f / 128.f) - mean * mean;
    float rstd = rsqrtf(fmaxf(var, 0.f) + 1e-5f);
    __syncwarp();
    bufB[lane] = buf[lane] + (aS - mean) * rstd * sg[lane] + sb[lane];
    int p = 32 + 3 * lane;
    bufB[p]     = buf[p]     + (aX - mean) * rstd * sg[p]     + sb[p];
    bufB[p + 1] = buf[p + 1] + (aY - mean) * rstd * sg[p + 1] + sb[p + 1];
    bufB[p + 2] = buf[p + 2] + (aZ - mean) * rstd * sg[p + 2] + sb[p + 2];
    __syncwarp();
    reinterpret_cast<float4*>(out)[(size_t)n * 32 + lane] = ((float4*)bufB)[lane];
}

__global__ void __launch_bounds__(256, 7) k_aggregate(const float* __restrict__ x,
                                                      const float* __restrict__ gamma,
                                                      const float* __restrict__ beta,
                                                      float* __restrict__ out) {
    __shared__ float4 srec[2][8][32];     // prefetched first chunks, both nodes
    __shared__ float4 smom[16][32][2];    // [nodeSlot][i][2]; reused as LN buffers
    __shared__ float sg[128], sb[128];
    for (int t = threadIdx.x; t < 128; t += 256) { sg[t] = gamma[t]; sb[t] = beta[t]; }
    int w = threadIdx.x >> 5;
    int lane = threadIdx.x & 31;

    // ---- prefetch: counts + first 32 recs of BOTH nodes, all in flight ----
    int n0 = blockIdx.x * 16 + w;
    int n1 = n0 + 8;
    int c0 = g_cur[n0];
    int c1 = g_cur[n1];
    srec[0][w][lane] = __ldg(&g_bucket[(size_t)n0 * CAP + lane]);  // garbage slots
    srec[1][w][lane] = __ldg(&g_bucket[(size_t)n1 * CAP + lane]);  // never read
    __syncthreads();   // covers sg/sb too

    // ---- edge-moment phase for two nodes ----
#pragma unroll 1
    for (int half = 0; half < 2; half++) {
        int n = half ? n1 : n0;
        int count = min(half ? c1 : c0, CAP);
        float aD = 0.f, aBx = 0.f, aBy = 0.f, aBz = 0.f, aCx = 0.f, aCy = 0.f, aCz = 0.f;
        // chunk 0 (already staged; covers all but ~1e-5 of nodes)
        int m = min(32, count);
#pragma unroll 4
        for (int k = 0; k < m; k++) {
            float4 r = srec[half][w][k];
            int c = __float_as_int(r.w);
            uint2 u = __ldg(&g_feat[(size_t)c * 32 + lane]);   // fp16x4
            float2 fa = __half22float2(*reinterpret_cast<__half2*>(&u.x)); // (s,vx)
            float2 fb = __half22float2(*reinterpret_cast<__half2*>(&u.y)); // (vy,vz)
            float fs = fa.x, vx = fa.y, vy = fb.x, vz = fb.y;
            aD  += vx * r.x + vy * r.y + vz * r.z;
            aBx += fs * r.x; aBy += fs * r.y; aBz += fs * r.z;
            aCx += vy * r.z - vz * r.y;
            aCy += vz * r.x - vx * r.z;
            aCz += vx * r.y - vy * r.x;
        }
        // rare tail chunks (deg > 32)
        for (int base = 32; base < count; base += 32) {
            __syncwarp();
            if (base + lane < count)
                srec[half][w][lane] = __ldg(&g_bucket[(size_t)n * CAP + base + lane]);
            __syncwarp();
            int mm = min(32, count - base);
            for (int k = 0; k < mm; k++) {
                float4 r = srec[half][w][k];
                int c = __float_as_int(r.w);
                uint2 u = __ldg(&g_feat[(size_t)c * 32 + lane]);
                float2 fa = __half22float2(*reinterpret_cast<__half2*>(&u.x));
                float2 fb = __half22float2(*reinterpret_cast<__half2*>(&u.y));
                float fs = fa.x, vx = fa.y, vy = fb.x, vz = fb.y;
                aD  += vx * r.x + vy * r.y + vz * r.z;
                aBx += fs * r.x; aBy += fs * r.y; aBz += fs * r.z;
                aCx += vy * r.z - vz * r.y;
                aCy += vz * r.x - vx * r.z;
                aCz += vx * r.y - vy * r.x;
            }
        }
        float invd = 1.f / fmaxf((float)count, 1.f);
        smom[half * 8 + w][lane][0] = make_float4(aD * invd, aBx * invd, aBy * invd, aBz * invd);
        smom[half * 8 + w][lane][1] = make_float4(aCx * invd, aCy * invd, aCz * invd, 0.f);
    }
    __syncwarp();

    // ---- contraction for both nodes; WA scalar + (WB,WC) paired loads ----
    float aS0 = 0.f, aX0 = 0.f, aY0 = 0.f, aZ0 = 0.f;
    float aS1 = 0.f, aX1 = 0.f, aY1 = 0.f, aZ1 = 0.f;
#pragma unroll
    for (int i = 0; i < 32; i++) {
        float  WAi = __ldg(&g_WA[i * 32 + lane]);
        float2 Wbc = __ldg(&g_WBC[i * 32 + lane]);
        float4 p0 = smom[w][i][0];       // broadcast LDS
        float4 p1 = smom[w][i][1];
        float4 q0 = smom[8 + w][i][0];
        float4 q1 = smom[8 + w][i][1];
        aS0 += p0.x * WAi;
        aX0 += p0.y * Wbc.x + p1.x * Wbc.y;
        aY0 += p0.z * Wbc.x + p1.y * Wbc.y;
        aZ0 += p0.w * Wbc.x + p1.z * Wbc.y;
        aS1 += q0.x * WAi;
        aX1 += q0.y * Wbc.x + q1.x * Wbc.y;
        aY1 += q0.z * Wbc.x + q1.y * Wbc.y;
        aZ1 += q0.w * Wbc.x + q1.z * Wbc.y;
    }
    __syncwarp();   // smom now dead; reuse as LN staging

    ln_write(n0, aS0, aX0, aY0, aZ0, x, sg, sb, out, lane, (float*)&smom[w][0][0]);
    ln_write(n1, aS1, aX1, aY1, aZ1, x, sg, sb, out, lane, (float*)&smom[8 + w][0][0]);
}

// ---------------------------------------------------------------------------
extern "C" void kernel_launch(void* const* d_in, const int* in_sizes, int n_in,
                              void* d_out, int out_size) {
    const float* x    = (const float*)d_in[0];
    const float* pos  = (const float*)d_in[1];
    const int*   ei   = (const int*)d_in[2];
    const float* Wns  = (const float*)d_in[3];
    const float* Wnv  = (const float*)d_in[4];
    const float* Wd   = (const float*)d_in[5];
    const float* Ws   = (const float*)d_in[6];
    const float* Wc   = (const float*)d_in[7];
    const float* Wms  = (const float*)d_in[8];
    const float* Wmv  = (const float*)d_in[9];
    const float* gam  = (const float*)d_in[10];
    const float* bet  = (const float*)d_in[11];
    float* out = (float*)d_out;

    int E = in_sizes[2] / 2;

    k_prep<<<(NN + 255) / 256 + 1, 256>>>(pos, Wd, Ws, Wc, Wms, Wmv);
    k_node<<<NN / 32, 256>>>(x, Wns, Wnv);
    k_scatter<<<(E + 255) / 256, 256>>>(ei, E);
    k_aggregate<<<NN / 16, 256>>>(x, gam, bet, out);
}